// round 6
// baseline (speedup 1.0000x reference)
#include <cuda_runtime.h>
#include <cuda_bf16.h>
#include <cstdint>

#define NN 50000
#define NE 800000
#define NH 4
#define DI 256
#define DO 64
#define CO 256   // NH * DO

#define NB_SCAN 196  // ceil(NN/256)

// ---- scratch (device globals; no runtime allocation) ----
__device__ float g_feats[NN * CO];       // [n][h*64+o]
__device__ float4 g_as4[NN];
__device__ float4 g_ad4[NN];
__device__ float g_w[NE * NH];           // CSR-ordered weights [pos][h]
__device__ int   g_cdst[NE];
__device__ int   g_deg[NN];
__device__ int   g_rowstart[NN + 1];
__device__ int   g_cursor[NN];
__device__ float g_bcat[CO];
__device__ int   g_part[NB_SCAN];
__device__ float g_v[8 * DI];
__device__ float g_c[8];
__device__ __nv_bfloat16 g_Bhi[CO * DI]; // Bt[n][k] hi  (n = h*64+o, k = d)
__device__ __nv_bfloat16 g_Blo[CO * DI]; // Bt[n][k] lo

// ==================== fused prep: B split + bcat + v/c + deg zero ====================
__global__ void prep_all_kernel(const float* __restrict__ Ws, const float* __restrict__ bs,
                                const float* __restrict__ aw) {
    int i = blockIdx.x * blockDim.x + threadIdx.x;
    if (i < CO * DI) {          // B transpose + bf16 split: Bt[n][k] = Ws[h][k][o]
        int n = i >> 8, k = i & 255;
        int h = n >> 6, o = n & 63;
        float v = Ws[(h * DI + k) * DO + o];
        __nv_bfloat16 hi = __float2bfloat16(v);
        __nv_bfloat16 lo = __float2bfloat16(v - __bfloat162float(hi));
        g_Bhi[i] = hi;
        g_Blo[i] = lo;
    }
    if (i < CO) {
        int h = i >> 6, o = i & 63;
        g_bcat[i] = bs[h * DO + o];
    }
    if (i < 8 * DI) {           // v[j][d] = sum_o Ws[h][d][o] * aw[h][sd*64+o]
        int j = i >> 8, d = i & 255;
        int h = j >> 1, sd = j & 1;
        const float* wrow = Ws + (h * DI + d) * DO;
        const float* arow = aw + h * (2 * DO + 1) + sd * DO;
        float s = 0.f;
#pragma unroll
        for (int o = 0; o < DO; o++) s += wrow[o] * arow[o];
        g_v[i] = s;
    } else if (i < 8 * DI + 8) { // c[j] = bs[h]·aw_{src/dst}[h]
        int j = i - 8 * DI;
        int h = j >> 1, sd = j & 1;
        const float* arow = aw + h * (2 * DO + 1) + sd * DO;
        float s = 0.f;
#pragma unroll
        for (int o = 0; o < DO; o++) s += bs[h * DO + o] * arow[o];
        g_c[j] = s;
    }
    if (i < NN) g_deg[i] = 0;
}

__global__ void count_kernel(const int* __restrict__ idx) {
    int e = blockIdx.x * blockDim.x + threadIdx.x;
    if (e < NE) atomicAdd(&g_deg[idx[e]], 1);
}

// ---------------- 3-phase decoupled scan ----------------
__global__ void scan1_kernel() {
    __shared__ int sd[256];
    int tid = threadIdx.x;
    int i = blockIdx.x * 256 + tid;
    sd[tid] = (i < NN) ? g_deg[i] : 0;
    __syncthreads();
    for (int off = 128; off; off >>= 1) {
        if (tid < off) sd[tid] += sd[tid + off];
        __syncthreads();
    }
    if (tid == 0) g_part[blockIdx.x] = sd[0];
}

__global__ void scan2_kernel() {
    __shared__ int sd[256];
    int tid = threadIdx.x;
    int v = (tid < NB_SCAN) ? g_part[tid] : 0;
    sd[tid] = v;
    __syncthreads();
    for (int off = 1; off < 256; off <<= 1) {
        int t = (tid >= off) ? sd[tid - off] : 0;
        __syncthreads();
        sd[tid] += t;
        __syncthreads();
    }
    if (tid < NB_SCAN) g_part[tid] = sd[tid] - v;
    if (tid == 255) g_rowstart[NN] = sd[255];
}

__global__ void scan3_kernel() {
    __shared__ int sd[256];
    int tid = threadIdx.x;
    int i = blockIdx.x * 256 + tid;
    int v = (i < NN) ? g_deg[i] : 0;
    sd[tid] = v;
    __syncthreads();
    for (int off = 1; off < 256; off <<= 1) {
        int t = (tid >= off) ? sd[tid - off] : 0;
        __syncthreads();
        sd[tid] += t;
        __syncthreads();
    }
    if (i < NN) {
        int ex = g_part[blockIdx.x] + sd[tid] - v;
        g_rowstart[i] = ex;
        g_cursor[i] = ex;
    }
}

// ---------------- a_s/a_d directly from x: warp per node ----------------
__global__ void __launch_bounds__(256) as_kernel(const float* __restrict__ x) {
    int gw = (blockIdx.x * blockDim.x + threadIdx.x) >> 5;
    int lane = threadIdx.x & 31;
    if (gw >= NN) return;
    const float* xr = x + (size_t)gw * DI;
    float a[8] = {};
#pragma unroll
    for (int c8 = 0; c8 < 8; c8++) {
        float xv = xr[c8 * 32 + lane];
#pragma unroll
        for (int j = 0; j < 8; j++)
            a[j] += xv * __ldg(&g_v[j * DI + c8 * 32 + lane]);
    }
#pragma unroll
    for (int j = 0; j < 8; j++) {
#pragma unroll
        for (int off = 16; off; off >>= 1)
            a[j] += __shfl_xor_sync(0xffffffffu, a[j], off);
    }
    if (lane == 0) {
        g_as4[gw] = make_float4(a[0] + g_c[0], a[2] + g_c[2],
                                a[4] + g_c[4], a[6] + g_c[6]);
        g_ad4[gw] = make_float4(a[1] + g_c[1], a[3] + g_c[3],
                                a[5] + g_c[5], a[7] + g_c[7]);
    }
}

// ==================== warp-level bf16 split MMA GEMM ====================
#define KS 32          // k-chunk
#define LDA 40         // smem row stride in bf16 elements

__device__ __forceinline__ void mma_bf16(float* c, const uint32_t* a, const uint32_t* b) {
    asm volatile(
        "mma.sync.aligned.m16n8k16.row.col.f32.bf16.bf16.f32 "
        "{%0,%1,%2,%3}, {%4,%5,%6,%7}, {%8,%9}, {%0,%1,%2,%3};"
        : "+f"(c[0]), "+f"(c[1]), "+f"(c[2]), "+f"(c[3])
        : "r"(a[0]), "r"(a[1]), "r"(a[2]), "r"(a[3]), "r"(b[0]), "r"(b[1]));
}

__global__ void __launch_bounds__(256, 2) gemm_mma_kernel(const float* __restrict__ x) {
    __shared__ __align__(16) __nv_bfloat16 sAhi[128 * LDA];
    __shared__ __align__(16) __nv_bfloat16 sAlo[128 * LDA];
    __shared__ __align__(16) __nv_bfloat16 sBhi[128 * LDA];
    __shared__ __align__(16) __nv_bfloat16 sBlo[128 * LDA];

    int tid = threadIdx.x;
    int wid = tid >> 5;
    int lane = tid & 31;
    int group = lane >> 2;
    int tid4 = lane & 3;
    int bm = blockIdx.y * 128;
    int bn = blockIdx.x * 128;
    int wm = (wid & 3) * 32;
    int wn = (wid >> 2) * 64;

    int lrow = tid >> 1;
    int lk0 = (tid & 1) * 16;
    int grow = bm + lrow;
    bool aok = grow < NN;
    const float4* xp = (const float4*)(x + (size_t)grow * DI);
    const uint4* bhp = (const uint4*)(g_Bhi + (size_t)(bn + lrow) * DI);
    const uint4* blp = (const uint4*)(g_Blo + (size_t)(bn + lrow) * DI);

    float acc[2][8][4] = {};

    for (int c = 0; c < DI / KS; c++) {
        if (c) __syncthreads();
        int ck = c * KS;
#pragma unroll
        for (int q = 0; q < 4; q++) {
            float4 v = aok ? __ldg(xp + ((ck + lk0) >> 2) + q)
                           : make_float4(0.f, 0.f, 0.f, 0.f);
            __nv_bfloat16 h0 = __float2bfloat16(v.x);
            __nv_bfloat16 h1 = __float2bfloat16(v.y);
            __nv_bfloat16 h2 = __float2bfloat16(v.z);
            __nv_bfloat16 h3 = __float2bfloat16(v.w);
            __nv_bfloat162 hiA; hiA.x = h0; hiA.y = h1;
            __nv_bfloat162 hiB; hiB.x = h2; hiB.y = h3;
            __nv_bfloat162 loA, loB;
            loA.x = __float2bfloat16(v.x - __bfloat162float(h0));
            loA.y = __float2bfloat16(v.y - __bfloat162float(h1));
            loB.x = __float2bfloat16(v.z - __bfloat162float(h2));
            loB.y = __float2bfloat16(v.w - __bfloat162float(h3));
            int e = lrow * LDA + lk0 + q * 4;
            *(__nv_bfloat162*)&sAhi[e]     = hiA;
            *(__nv_bfloat162*)&sAhi[e + 2] = hiB;
            *(__nv_bfloat162*)&sAlo[e]     = loA;
            *(__nv_bfloat162*)&sAlo[e + 2] = loB;
        }
        {
            uint4 vh0 = __ldg(bhp + ((ck + lk0) >> 3));
            uint4 vh1 = __ldg(bhp + ((ck + lk0) >> 3) + 1);
            uint4 vl0 = __ldg(blp + ((ck + lk0) >> 3));
            uint4 vl1 = __ldg(blp + ((ck + lk0) >> 3) + 1);
            int e = lrow * LDA + lk0;
            *(uint4*)&sBhi[e]     = vh0;
            *(uint4*)&sBhi[e + 8] = vh1;
            *(uint4*)&sBlo[e]     = vl0;
            *(uint4*)&sBlo[e + 8] = vl1;
        }
        __syncthreads();

#pragma unroll
        for (int k16 = 0; k16 < KS; k16 += 16) {
            uint32_t ah[2][4], al[2][4];
#pragma unroll
            for (int mi = 0; mi < 2; mi++) {
                int r0 = (wm + mi * 16 + group) * LDA + k16 + tid4 * 2;
                ah[mi][0] = *(const uint32_t*)&sAhi[r0];
                ah[mi][1] = *(const uint32_t*)&sAhi[r0 + 8 * LDA];
                ah[mi][2] = *(const uint32_t*)&sAhi[r0 + 8];
                ah[mi][3] = *(const uint32_t*)&sAhi[r0 + 8 * LDA + 8];
                al[mi][0] = *(const uint32_t*)&sAlo[r0];
                al[mi][1] = *(const uint32_t*)&sAlo[r0 + 8 * LDA];
                al[mi][2] = *(const uint32_t*)&sAlo[r0 + 8];
                al[mi][3] = *(const uint32_t*)&sAlo[r0 + 8 * LDA + 8];
            }
#pragma unroll
            for (int ni = 0; ni < 8; ni++) {
                int rb = (wn + ni * 8 + group) * LDA + k16 + tid4 * 2;
                uint32_t bh[2], bl[2];
                bh[0] = *(const uint32_t*)&sBhi[rb];
                bh[1] = *(const uint32_t*)&sBhi[rb + 8];
                bl[0] = *(const uint32_t*)&sBlo[rb];
                bl[1] = *(const uint32_t*)&sBlo[rb + 8];
#pragma unroll
                for (int mi = 0; mi < 2; mi++) {
                    mma_bf16(acc[mi][ni], ah[mi], bh);
                    mma_bf16(acc[mi][ni], ah[mi], bl);
                    mma_bf16(acc[mi][ni], al[mi], bh);
                }
            }
        }
    }

#pragma unroll
    for (int mi = 0; mi < 2; mi++) {
        int row0 = bm + wm + mi * 16 + group;
        int row1 = row0 + 8;
#pragma unroll
        for (int ni = 0; ni < 8; ni++) {
            int col = bn + wn + ni * 8 + tid4 * 2;
            float2 bb = *(const float2*)(g_bcat + col);
            if (row0 < NN) {
                float2 o0 = make_float2(acc[mi][ni][0] + bb.x, acc[mi][ni][1] + bb.y);
                *(float2*)(g_feats + (size_t)row0 * CO + col) = o0;
            }
            if (row1 < NN) {
                float2 o1 = make_float2(acc[mi][ni][2] + bb.x, acc[mi][ni][3] + bb.y);
                *(float2*)(g_feats + (size_t)row1 * CO + col) = o1;
            }
        }
    }
}

// ---------------- edge weights + flat CSR fill ----------------
__global__ void edge_kernel(const int* __restrict__ idx, const float* __restrict__ elem,
                            const float* __restrict__ aw, const float* __restrict__ ab) {
    int e = blockIdx.x * blockDim.x + threadIdx.x;
    if (e >= NE) return;
    int s = idx[e];
    int d = idx[NE + e];
    float el = elem[e];
    float4 as = __ldg(&g_as4[s]);
    float4 ad = __ldg(&g_ad4[d]);
    const float* asv = (const float*)&as;
    const float* adv = (const float*)&ad;
    float w[NH];
#pragma unroll
    for (int h = 0; h < NH; h++) {
        float sc = asv[h] + adv[h]
                 + __ldg(&aw[h * (2 * DO + 1) + 2 * DO]) * el + __ldg(&ab[h]);
        sc = sc * (1.0f / 20.0f);
        w[h] = __expf(-fmaxf(sc, 0.0f));
    }
    int pos = atomicAdd(&g_cursor[s], 1);
    g_cdst[pos] = d;
    *(float4*)(g_w + (size_t)pos * 4) = make_float4(w[0], w[1], w[2], w[3]);
}

// ---------------- per-node gather + normalize ----------------
__global__ void __launch_bounds__(256) gather_kernel(float* __restrict__ out) {
    int t = threadIdx.x;
    int n = blockIdx.x * 4 + (t >> 6);
    int l = t & 63;
    int h = l >> 4;
    int start = g_rowstart[n];
    int end = g_rowstart[n + 1];

    const float4* fp = (const float4*)g_feats;
    float4 acc = make_float4(0.f, 0.f, 0.f, 0.f);
    float wsum = 0.f;

#pragma unroll 8
    for (int j = start; j < end; j++) {
        int dst = __ldg(&g_cdst[j]);
        float w = __ldg(&g_w[(size_t)j * 4 + h]);
        float4 f = __ldg(fp + (size_t)dst * 64 + l);
        acc.x += w * f.x;
        acc.y += w * f.y;
        acc.z += w * f.z;
        acc.w += w * f.w;
        wsum += w;
    }
    float4 o = make_float4(acc.x / wsum, acc.y / wsum, acc.z / wsum, acc.w / wsum);
    *(float4*)(out + (size_t)n * CO + l * 4) = o;
}

extern "C" void kernel_launch(void* const* d_in, const int* in_sizes, int n_in,
                              void* d_out, int out_size) {
    const float* x    = (const float*)d_in[0];
    const int*   idx  = (const int*)d_in[1];
    const float* elem = (const float*)d_in[2];
    const float* Ws   = (const float*)d_in[3];
    const float* bs   = (const float*)d_in[4];
    const float* aw   = (const float*)d_in[5];
    const float* ab   = (const float*)d_in[6];
    float* out = (float*)d_out;

    static cudaStream_t s1 = nullptr, s2 = nullptr;
    static cudaEvent_t evP = nullptr, evAs = nullptr, evJ = nullptr;
    if (!s1) {   // created on the (uncaptured) correctness call, reused thereafter
        cudaStreamCreateWithFlags(&s1, cudaStreamNonBlocking);
        cudaStreamCreateWithFlags(&s2, cudaStreamNonBlocking);
        cudaEventCreateWithFlags(&evP, cudaEventDisableTiming);
        cudaEventCreateWithFlags(&evAs, cudaEventDisableTiming);
        cudaEventCreateWithFlags(&evJ, cudaEventDisableTiming);
    }

    // stage 0: fused prep (B split, bcat, v/c, deg=0) on legacy stream
    prep_all_kernel<<<(CO * DI + 255) / 256, 256>>>(Ws, bs, aw);
    cudaEventRecord(evP, 0);
    cudaStreamWaitEvent(s1, evP, 0);
    cudaStreamWaitEvent(s2, evP, 0);

    // s1: CSR chain (count -> scan)
    count_kernel<<<(NE + 255) / 256, 256, 0, s1>>>(idx);
    scan1_kernel<<<NB_SCAN, 256, 0, s1>>>();
    scan2_kernel<<<1, 256, 0, s1>>>();
    scan3_kernel<<<NB_SCAN, 256, 0, s1>>>();

    // legacy stream: GEMM (launch #6 for ncu)
    gemm_mma_kernel<<<dim3(2, (NN + 127) / 128), 256>>>(x);

    // s2: attention dots (overlaps count/scan and gemm)
    as_kernel<<<(NN * 32 + 255) / 256, 256, 0, s2>>>(x);
    cudaEventRecord(evAs, s2);

    // s1: edge needs scan (same stream) + as (cross-stream)
    cudaStreamWaitEvent(s1, evAs, 0);
    edge_kernel<<<(NE + 255) / 256, 256, 0, s1>>>(idx, elem, aw, ab);
    cudaEventRecord(evJ, s1);

    // join: gather needs feats (legacy) + CSR/w (s1)
    cudaStreamWaitEvent(0, evJ, 0);
    gather_kernel<<<NN / 4, 256>>>(out);
}

// round 7
// speedup vs baseline: 1.0350x; 1.0350x over previous
#include <cuda_runtime.h>
#include <cuda_bf16.h>
#include <cstdint>

#define NN 50000
#define NE 800000
#define NH 4
#define DI 256
#define DO 64
#define CO 256   // NH * DO

#define NB_SCAN 196  // ceil(NN/256)

// ---- scratch (device globals; no runtime allocation) ----
__device__ float g_feats[NN * CO];       // [n][h*64+o]
__device__ float4 g_as4[NN];
__device__ float4 g_ad4[NN];
__device__ float g_w[NE * NH];           // CSR-ordered weights [pos][h]
__device__ int   g_cdst[NE];
__device__ int   g_deg[NN];
__device__ int   g_rowstart[NN + 1];
__device__ int   g_cursor[NN];
__device__ float g_bcat[CO];
__device__ int   g_part[NB_SCAN];
__device__ float g_v[8 * DI];
__device__ float g_c[8];
__device__ __nv_bfloat16 g_Bhi[CO * DI]; // Bt[n][k] hi  (n = h*64+o, k = d)
__device__ __nv_bfloat16 g_Blo[CO * DI]; // Bt[n][k] lo

// ==================== small prep kernels ====================
__global__ void prep_kernel(const float* __restrict__ bs) {
    int i = blockIdx.x * blockDim.x + threadIdx.x;
    if (i < CO) {
        int h = i >> 6, o = i & 63;
        g_bcat[i] = bs[h * DO + o];
    }
}

// B transposed + bf16 split: Bt[n][k] = Ws[h][k][o], n = h*64+o
__global__ void prepB_kernel(const float* __restrict__ Ws) {
    int i = blockIdx.x * blockDim.x + threadIdx.x;
    if (i >= CO * DI) return;
    int n = i >> 8, k = i & 255;
    int h = n >> 6, o = n & 63;
    float v = Ws[(h * DI + k) * DO + o];
    __nv_bfloat16 hi = __float2bfloat16(v);
    __nv_bfloat16 lo = __float2bfloat16(v - __bfloat162float(hi));
    g_Bhi[i] = hi;
    g_Blo[i] = lo;
}

__global__ void prepv_kernel(const float* __restrict__ Ws, const float* __restrict__ bs,
                             const float* __restrict__ aw) {
    int id = blockIdx.x * blockDim.x + threadIdx.x;
    if (id < 8 * DI) {
        int j = id >> 8, d = id & 255;
        int h = j >> 1, sd = j & 1;
        const float* wrow = Ws + (h * DI + d) * DO;
        const float* arow = aw + h * (2 * DO + 1) + sd * DO;
        float s = 0.f;
#pragma unroll
        for (int o = 0; o < DO; o++) s += wrow[o] * arow[o];
        g_v[id] = s;
    } else if (id < 8 * DI + 8) {
        int j = id - 8 * DI;
        int h = j >> 1, sd = j & 1;
        const float* arow = aw + h * (2 * DO + 1) + sd * DO;
        float s = 0.f;
#pragma unroll
        for (int o = 0; o < DO; o++) s += bs[h * DO + o] * arow[o];
        g_c[j] = s;
    }
}

__global__ void zero_deg_kernel() {
    int i = blockIdx.x * blockDim.x + threadIdx.x;
    if (i < NN) g_deg[i] = 0;
}

__global__ void count_kernel(const int* __restrict__ idx) {
    int e = blockIdx.x * blockDim.x + threadIdx.x;
    if (e < NE) atomicAdd(&g_deg[idx[e]], 1);
}

// ---------------- 3-phase decoupled scan ----------------
__global__ void scan1_kernel() {
    __shared__ int sd[256];
    int tid = threadIdx.x;
    int i = blockIdx.x * 256 + tid;
    sd[tid] = (i < NN) ? g_deg[i] : 0;
    __syncthreads();
    for (int off = 128; off; off >>= 1) {
        if (tid < off) sd[tid] += sd[tid + off];
        __syncthreads();
    }
    if (tid == 0) g_part[blockIdx.x] = sd[0];
}

__global__ void scan2_kernel() {
    __shared__ int sd[256];
    int tid = threadIdx.x;
    int v = (tid < NB_SCAN) ? g_part[tid] : 0;
    sd[tid] = v;
    __syncthreads();
    for (int off = 1; off < 256; off <<= 1) {
        int t = (tid >= off) ? sd[tid - off] : 0;
        __syncthreads();
        sd[tid] += t;
        __syncthreads();
    }
    if (tid < NB_SCAN) g_part[tid] = sd[tid] - v;
    if (tid == 255) g_rowstart[NN] = sd[255];
}

__global__ void scan3_kernel() {
    __shared__ int sd[256];
    int tid = threadIdx.x;
    int i = blockIdx.x * 256 + tid;
    int v = (i < NN) ? g_deg[i] : 0;
    sd[tid] = v;
    __syncthreads();
    for (int off = 1; off < 256; off <<= 1) {
        int t = (tid >= off) ? sd[tid - off] : 0;
        __syncthreads();
        sd[tid] += t;
        __syncthreads();
    }
    if (i < NN) {
        int ex = g_part[blockIdx.x] + sd[tid] - v;
        g_rowstart[i] = ex;
        g_cursor[i] = ex;
    }
}

// ---------------- a_s/a_d directly from x: warp per node ----------------
__global__ void __launch_bounds__(256) as_kernel(const float* __restrict__ x) {
    int gw = (blockIdx.x * blockDim.x + threadIdx.x) >> 5;
    int lane = threadIdx.x & 31;
    if (gw >= NN) return;
    const float* xr = x + (size_t)gw * DI;
    float a[8] = {};
#pragma unroll
    for (int c8 = 0; c8 < 8; c8++) {
        float xv = xr[c8 * 32 + lane];
#pragma unroll
        for (int j = 0; j < 8; j++)
            a[j] += xv * __ldg(&g_v[j * DI + c8 * 32 + lane]);
    }
#pragma unroll
    for (int j = 0; j < 8; j++) {
#pragma unroll
        for (int off = 16; off; off >>= 1)
            a[j] += __shfl_xor_sync(0xffffffffu, a[j], off);
    }
    if (lane == 0) {
        g_as4[gw] = make_float4(a[0] + g_c[0], a[2] + g_c[2],
                                a[4] + g_c[4], a[6] + g_c[6]);
        g_ad4[gw] = make_float4(a[1] + g_c[1], a[3] + g_c[3],
                                a[5] + g_c[5], a[7] + g_c[7]);
    }
}

// ==================== warp-level bf16 split MMA GEMM ====================
#define KS 32          // k-chunk
#define LDA 40         // smem row stride in bf16 elements

__device__ __forceinline__ void mma_bf16(float* c, const uint32_t* a, const uint32_t* b) {
    asm volatile(
        "mma.sync.aligned.m16n8k16.row.col.f32.bf16.bf16.f32 "
        "{%0,%1,%2,%3}, {%4,%5,%6,%7}, {%8,%9}, {%0,%1,%2,%3};"
        : "+f"(c[0]), "+f"(c[1]), "+f"(c[2]), "+f"(c[3])
        : "r"(a[0]), "r"(a[1]), "r"(a[2]), "r"(a[3]), "r"(b[0]), "r"(b[1]));
}

__global__ void __launch_bounds__(256, 2) gemm_mma_kernel(const float* __restrict__ x) {
    __shared__ __align__(16) __nv_bfloat16 sAhi[128 * LDA];
    __shared__ __align__(16) __nv_bfloat16 sAlo[128 * LDA];
    __shared__ __align__(16) __nv_bfloat16 sBhi[128 * LDA];
    __shared__ __align__(16) __nv_bfloat16 sBlo[128 * LDA];

    int tid = threadIdx.x;
    int wid = tid >> 5;
    int lane = tid & 31;
    int group = lane >> 2;
    int tid4 = lane & 3;
    int bm = blockIdx.y * 128;
    int bn = blockIdx.x * 128;
    int wm = (wid & 3) * 32;
    int wn = (wid >> 2) * 64;

    int lrow = tid >> 1;
    int lk0 = (tid & 1) * 16;
    int grow = bm + lrow;
    bool aok = grow < NN;
    const float4* xp = (const float4*)(x + (size_t)grow * DI);
    const uint4* bhp = (const uint4*)(g_Bhi + (size_t)(bn + lrow) * DI);
    const uint4* blp = (const uint4*)(g_Blo + (size_t)(bn + lrow) * DI);

    float acc[2][8][4] = {};

    for (int c = 0; c < DI / KS; c++) {
        if (c) __syncthreads();
        int ck = c * KS;
#pragma unroll
        for (int q = 0; q < 4; q++) {
            float4 v = aok ? __ldg(xp + ((ck + lk0) >> 2) + q)
                           : make_float4(0.f, 0.f, 0.f, 0.f);
            __nv_bfloat16 h0 = __float2bfloat16(v.x);
            __nv_bfloat16 h1 = __float2bfloat16(v.y);
            __nv_bfloat16 h2 = __float2bfloat16(v.z);
            __nv_bfloat16 h3 = __float2bfloat16(v.w);
            __nv_bfloat162 hiA; hiA.x = h0; hiA.y = h1;
            __nv_bfloat162 hiB; hiB.x = h2; hiB.y = h3;
            __nv_bfloat162 loA, loB;
            loA.x = __float2bfloat16(v.x - __bfloat162float(h0));
            loA.y = __float2bfloat16(v.y - __bfloat162float(h1));
            loB.x = __float2bfloat16(v.z - __bfloat162float(h2));
            loB.y = __float2bfloat16(v.w - __bfloat162float(h3));
            int e = lrow * LDA + lk0 + q * 4;
            *(__nv_bfloat162*)&sAhi[e]     = hiA;
            *(__nv_bfloat162*)&sAhi[e + 2] = hiB;
            *(__nv_bfloat162*)&sAlo[e]     = loA;
            *(__nv_bfloat162*)&sAlo[e + 2] = loB;
        }
        {
            uint4 vh0 = __ldg(bhp + ((ck + lk0) >> 3));
            uint4 vh1 = __ldg(bhp + ((ck + lk0) >> 3) + 1);
            uint4 vl0 = __ldg(blp + ((ck + lk0) >> 3));
            uint4 vl1 = __ldg(blp + ((ck + lk0) >> 3) + 1);
            int e = lrow * LDA + lk0;
            *(uint4*)&sBhi[e]     = vh0;
            *(uint4*)&sBhi[e + 8] = vh1;
            *(uint4*)&sBlo[e]     = vl0;
            *(uint4*)&sBlo[e + 8] = vl1;
        }
        __syncthreads();

#pragma unroll
        for (int k16 = 0; k16 < KS; k16 += 16) {
            uint32_t ah[2][4], al[2][4];
#pragma unroll
            for (int mi = 0; mi < 2; mi++) {
                int r0 = (wm + mi * 16 + group) * LDA + k16 + tid4 * 2;
                ah[mi][0] = *(const uint32_t*)&sAhi[r0];
                ah[mi][1] = *(const uint32_t*)&sAhi[r0 + 8 * LDA];
                ah[mi][2] = *(const uint32_t*)&sAhi[r0 + 8];
                ah[mi][3] = *(const uint32_t*)&sAhi[r0 + 8 * LDA + 8];
                al[mi][0] = *(const uint32_t*)&sAlo[r0];
                al[mi][1] = *(const uint32_t*)&sAlo[r0 + 8 * LDA];
                al[mi][2] = *(const uint32_t*)&sAlo[r0 + 8];
                al[mi][3] = *(const uint32_t*)&sAlo[r0 + 8 * LDA + 8];
            }
#pragma unroll
            for (int ni = 0; ni < 8; ni++) {
                int rb = (wn + ni * 8 + group) * LDA + k16 + tid4 * 2;
                uint32_t bh[2], bl[2];
                bh[0] = *(const uint32_t*)&sBhi[rb];
                bh[1] = *(const uint32_t*)&sBhi[rb + 8];
                bl[0] = *(const uint32_t*)&sBlo[rb];
                bl[1] = *(const uint32_t*)&sBlo[rb + 8];
#pragma unroll
                for (int mi = 0; mi < 2; mi++) {
                    mma_bf16(acc[mi][ni], ah[mi], bh);
                    mma_bf16(acc[mi][ni], ah[mi], bl);
                    mma_bf16(acc[mi][ni], al[mi], bh);
                }
            }
        }
    }

#pragma unroll
    for (int mi = 0; mi < 2; mi++) {
        int row0 = bm + wm + mi * 16 + group;
        int row1 = row0 + 8;
#pragma unroll
        for (int ni = 0; ni < 8; ni++) {
            int col = bn + wn + ni * 8 + tid4 * 2;
            float2 bb = *(const float2*)(g_bcat + col);
            if (row0 < NN) {
                float2 o0 = make_float2(acc[mi][ni][0] + bb.x, acc[mi][ni][1] + bb.y);
                *(float2*)(g_feats + (size_t)row0 * CO + col) = o0;
            }
            if (row1 < NN) {
                float2 o1 = make_float2(acc[mi][ni][2] + bb.x, acc[mi][ni][3] + bb.y);
                *(float2*)(g_feats + (size_t)row1 * CO + col) = o1;
            }
        }
    }
}

// ---------------- edge weights + flat CSR fill ----------------
__global__ void edge_kernel(const int* __restrict__ idx, const float* __restrict__ elem,
                            const float* __restrict__ aw, const float* __restrict__ ab) {
    int e = blockIdx.x * blockDim.x + threadIdx.x;
    if (e >= NE) return;
    int s = idx[e];
    int d = idx[NE + e];
    float el = elem[e];
    float4 as = __ldg(&g_as4[s]);
    float4 ad = __ldg(&g_ad4[d]);
    const float* asv = (const float*)&as;
    const float* adv = (const float*)&ad;
    float w[NH];
#pragma unroll
    for (int h = 0; h < NH; h++) {
        float sc = asv[h] + adv[h]
                 + __ldg(&aw[h * (2 * DO + 1) + 2 * DO]) * el + __ldg(&ab[h]);
        sc = sc * (1.0f / 20.0f);
        w[h] = __expf(-fmaxf(sc, 0.0f));
    }
    int pos = atomicAdd(&g_cursor[s], 1);
    g_cdst[pos] = d;
    *(float4*)(g_w + (size_t)pos * 4) = make_float4(w[0], w[1], w[2], w[3]);
}

// ---------------- per-node gather + normalize ----------------
__global__ void __launch_bounds__(256) gather_kernel(float* __restrict__ out) {
    int t = threadIdx.x;
    int n = blockIdx.x * 4 + (t >> 6);
    int l = t & 63;
    int h = l >> 4;
    int start = g_rowstart[n];
    int end = g_rowstart[n + 1];

    const float4* fp = (const float4*)g_feats;
    float4 acc = make_float4(0.f, 0.f, 0.f, 0.f);
    float wsum = 0.f;

#pragma unroll 4
    for (int j = start; j < end; j++) {
        int dst = __ldg(&g_cdst[j]);
        float w = __ldg(&g_w[(size_t)j * 4 + h]);
        float4 f = __ldg(fp + (size_t)dst * 64 + l);
        acc.x += w * f.x;
        acc.y += w * f.y;
        acc.z += w * f.z;
        acc.w += w * f.w;
        wsum += w;
    }
    float4 o = make_float4(acc.x / wsum, acc.y / wsum, acc.z / wsum, acc.w / wsum);
    *(float4*)(out + (size_t)n * CO + l * 4) = o;
}

extern "C" void kernel_launch(void* const* d_in, const int* in_sizes, int n_in,
                              void* d_out, int out_size) {
    const float* x    = (const float*)d_in[0];
    const int*   idx  = (const int*)d_in[1];
    const float* elem = (const float*)d_in[2];
    const float* Ws   = (const float*)d_in[3];
    const float* bs   = (const float*)d_in[4];
    const float* aw   = (const float*)d_in[5];
    const float* ab   = (const float*)d_in[6];
    float* out = (float*)d_out;

    static cudaStream_t s1 = nullptr, s2 = nullptr;
    static cudaEvent_t evF = nullptr, evPv = nullptr, evAs = nullptr, evJ = nullptr;
    if (!s1) {   // created on the (uncaptured) correctness call, reused thereafter
        cudaStreamCreateWithFlags(&s1, cudaStreamNonBlocking);
        cudaStreamCreateWithFlags(&s2, cudaStreamNonBlocking);
        cudaEventCreateWithFlags(&evF, cudaEventDisableTiming);
        cudaEventCreateWithFlags(&evPv, cudaEventDisableTiming);
        cudaEventCreateWithFlags(&evAs, cudaEventDisableTiming);
        cudaEventCreateWithFlags(&evJ, cudaEventDisableTiming);
    }

    // fork from origin (legacy) stream
    cudaEventRecord(evF, 0);
    cudaStreamWaitEvent(s1, evF, 0);

    // s1: prepv first, then CSR chain
    prepv_kernel<<<(8 * DI + 8 + 255) / 256, 256, 0, s1>>>(Ws, bs, aw);
    cudaEventRecord(evPv, s1);
    zero_deg_kernel<<<(NN + 255) / 256, 256, 0, s1>>>();
    count_kernel<<<(NE + 255) / 256, 256, 0, s1>>>(idx);
    scan1_kernel<<<NB_SCAN, 256, 0, s1>>>();
    scan2_kernel<<<1, 256, 0, s1>>>();
    scan3_kernel<<<NB_SCAN, 256, 0, s1>>>();

    // s2: attention dots (needs only prepv; overlaps count/scan)
    cudaStreamWaitEvent(s2, evPv, 0);
    as_kernel<<<(NN * 32 + 255) / 256, 256, 0, s2>>>(x);
    cudaEventRecord(evAs, s2);

    // s1: edge needs scan (same stream) + as (cross-stream)
    cudaStreamWaitEvent(s1, evAs, 0);
    edge_kernel<<<(NE + 255) / 256, 256, 0, s1>>>(idx, elem, aw, ab);
    cudaEventRecord(evJ, s1);

    // legacy stream: GEMM chain (overlaps s1/s2)
    prep_kernel<<<1, 256>>>(bs);
    prepB_kernel<<<(CO * DI + 255) / 256, 256>>>(Ws);
    gemm_mma_kernel<<<dim3(2, (NN + 127) / 128), 256>>>(x);

    // join, then gather (needs feats + CSR + weights)
    cudaStreamWaitEvent(0, evJ, 0);
    gather_kernel<<<NN / 4, 256>>>(out);
}

// round 8
// speedup vs baseline: 1.1371x; 1.0986x over previous
#include <cuda_runtime.h>
#include <cuda_bf16.h>
#include <cuda_fp16.h>
#include <cstdint>

#define NN 50000
#define NE 800000
#define NH 4
#define DI 256
#define DO 64
#define CO 256   // NH * DO

#define NB_SCAN 196  // ceil(NN/256)

// ---- scratch (device globals; no runtime allocation) ----
__device__ __half g_featsh[NN * CO];     // [n][h*64+o] fp16
__device__ float4 g_as4[NN];
__device__ float4 g_ad4[NN];
__device__ float g_w[NE * NH];           // CSR-ordered weights [pos][h]
__device__ int   g_cdst[NE];
__device__ int   g_deg[NN];
__device__ int   g_rowstart[NN + 1];
__device__ int   g_cursor[NN];
__device__ float g_bcat[CO];
__device__ int   g_part[NB_SCAN];
__device__ float g_v[8 * DI];
__device__ float g_c[8];
__device__ __nv_bfloat16 g_Bhi[CO * DI]; // Bt[n][k] hi  (n = h*64+o, k = d)
__device__ __nv_bfloat16 g_Blo[CO * DI]; // Bt[n][k] lo

// ==================== small prep kernels ====================
__global__ void prep_kernel(const float* __restrict__ bs) {
    int i = blockIdx.x * blockDim.x + threadIdx.x;
    if (i < CO) {
        int h = i >> 6, o = i & 63;
        g_bcat[i] = bs[h * DO + o];
    }
}

// B transposed + bf16 split: Bt[n][k] = Ws[h][k][o], n = h*64+o
__global__ void prepB_kernel(const float* __restrict__ Ws) {
    int i = blockIdx.x * blockDim.x + threadIdx.x;
    if (i >= CO * DI) return;
    int n = i >> 8, k = i & 255;
    int h = n >> 6, o = n & 63;
    float v = Ws[(h * DI + k) * DO + o];
    __nv_bfloat16 hi = __float2bfloat16(v);
    __nv_bfloat16 lo = __float2bfloat16(v - __bfloat162float(hi));
    g_Bhi[i] = hi;
    g_Blo[i] = lo;
}

__global__ void prepv_kernel(const float* __restrict__ Ws, const float* __restrict__ bs,
                             const float* __restrict__ aw) {
    int id = blockIdx.x * blockDim.x + threadIdx.x;
    if (id < 8 * DI) {
        int j = id >> 8, d = id & 255;
        int h = j >> 1, sd = j & 1;
        const float* wrow = Ws + (h * DI + d) * DO;
        const float* arow = aw + h * (2 * DO + 1) + sd * DO;
        float s = 0.f;
#pragma unroll
        for (int o = 0; o < DO; o++) s += wrow[o] * arow[o];
        g_v[id] = s;
    } else if (id < 8 * DI + 8) {
        int j = id - 8 * DI;
        int h = j >> 1, sd = j & 1;
        const float* arow = aw + h * (2 * DO + 1) + sd * DO;
        float s = 0.f;
#pragma unroll
        for (int o = 0; o < DO; o++) s += bs[h * DO + o] * arow[o];
        g_c[j] = s;
    }
}

__global__ void zero_deg_kernel() {
    int i = blockIdx.x * blockDim.x + threadIdx.x;
    if (i < NN) g_deg[i] = 0;
}

__global__ void count_kernel(const int* __restrict__ idx) {
    int e = blockIdx.x * blockDim.x + threadIdx.x;
    if (e < NE) atomicAdd(&g_deg[idx[e]], 1);
}

// ---------------- 3-phase decoupled scan ----------------
__global__ void scan1_kernel() {
    __shared__ int sd[256];
    int tid = threadIdx.x;
    int i = blockIdx.x * 256 + tid;
    sd[tid] = (i < NN) ? g_deg[i] : 0;
    __syncthreads();
    for (int off = 128; off; off >>= 1) {
        if (tid < off) sd[tid] += sd[tid + off];
        __syncthreads();
    }
    if (tid == 0) g_part[blockIdx.x] = sd[0];
}

__global__ void scan2_kernel() {
    __shared__ int sd[256];
    int tid = threadIdx.x;
    int v = (tid < NB_SCAN) ? g_part[tid] : 0;
    sd[tid] = v;
    __syncthreads();
    for (int off = 1; off < 256; off <<= 1) {
        int t = (tid >= off) ? sd[tid - off] : 0;
        __syncthreads();
        sd[tid] += t;
        __syncthreads();
    }
    if (tid < NB_SCAN) g_part[tid] = sd[tid] - v;
    if (tid == 255) g_rowstart[NN] = sd[255];
}

__global__ void scan3_kernel() {
    __shared__ int sd[256];
    int tid = threadIdx.x;
    int i = blockIdx.x * 256 + tid;
    int v = (i < NN) ? g_deg[i] : 0;
    sd[tid] = v;
    __syncthreads();
    for (int off = 1; off < 256; off <<= 1) {
        int t = (tid >= off) ? sd[tid - off] : 0;
        __syncthreads();
        sd[tid] += t;
        __syncthreads();
    }
    if (i < NN) {
        int ex = g_part[blockIdx.x] + sd[tid] - v;
        g_rowstart[i] = ex;
        g_cursor[i] = ex;
    }
}

// ---------------- a_s/a_d directly from x: warp per node ----------------
__global__ void __launch_bounds__(256) as_kernel(const float* __restrict__ x) {
    int gw = (blockIdx.x * blockDim.x + threadIdx.x) >> 5;
    int lane = threadIdx.x & 31;
    if (gw >= NN) return;
    const float* xr = x + (size_t)gw * DI;
    float a[8] = {};
#pragma unroll
    for (int c8 = 0; c8 < 8; c8++) {
        float xv = xr[c8 * 32 + lane];
#pragma unroll
        for (int j = 0; j < 8; j++)
            a[j] += xv * __ldg(&g_v[j * DI + c8 * 32 + lane]);
    }
#pragma unroll
    for (int j = 0; j < 8; j++) {
#pragma unroll
        for (int off = 16; off; off >>= 1)
            a[j] += __shfl_xor_sync(0xffffffffu, a[j], off);
    }
    if (lane == 0) {
        g_as4[gw] = make_float4(a[0] + g_c[0], a[2] + g_c[2],
                                a[4] + g_c[4], a[6] + g_c[6]);
        g_ad4[gw] = make_float4(a[1] + g_c[1], a[3] + g_c[3],
                                a[5] + g_c[5], a[7] + g_c[7]);
    }
}

// ==================== warp-level bf16 split MMA GEMM ====================
#define KS 32          // k-chunk
#define LDA 40         // smem row stride in bf16 elements

__device__ __forceinline__ void mma_bf16(float* c, const uint32_t* a, const uint32_t* b) {
    asm volatile(
        "mma.sync.aligned.m16n8k16.row.col.f32.bf16.bf16.f32 "
        "{%0,%1,%2,%3}, {%4,%5,%6,%7}, {%8,%9}, {%0,%1,%2,%3};"
        : "+f"(c[0]), "+f"(c[1]), "+f"(c[2]), "+f"(c[3])
        : "r"(a[0]), "r"(a[1]), "r"(a[2]), "r"(a[3]), "r"(b[0]), "r"(b[1]));
}

__global__ void __launch_bounds__(256, 2) gemm_mma_kernel(const float* __restrict__ x) {
    __shared__ __align__(16) __nv_bfloat16 sAhi[128 * LDA];
    __shared__ __align__(16) __nv_bfloat16 sAlo[128 * LDA];
    __shared__ __align__(16) __nv_bfloat16 sBhi[128 * LDA];
    __shared__ __align__(16) __nv_bfloat16 sBlo[128 * LDA];

    int tid = threadIdx.x;
    int wid = tid >> 5;
    int lane = tid & 31;
    int group = lane >> 2;
    int tid4 = lane & 3;
    int bm = blockIdx.y * 128;
    int bn = blockIdx.x * 128;
    int wm = (wid & 3) * 32;
    int wn = (wid >> 2) * 64;

    int lrow = tid >> 1;
    int lk0 = (tid & 1) * 16;
    int grow = bm + lrow;
    bool aok = grow < NN;
    const float4* xp = (const float4*)(x + (size_t)grow * DI);
    const uint4* bhp = (const uint4*)(g_Bhi + (size_t)(bn + lrow) * DI);
    const uint4* blp = (const uint4*)(g_Blo + (size_t)(bn + lrow) * DI);

    float acc[2][8][4] = {};

    for (int c = 0; c < DI / KS; c++) {
        if (c) __syncthreads();
        int ck = c * KS;
#pragma unroll
        for (int q = 0; q < 4; q++) {
            float4 v = aok ? __ldg(xp + ((ck + lk0) >> 2) + q)
                           : make_float4(0.f, 0.f, 0.f, 0.f);
            __nv_bfloat16 h0 = __float2bfloat16(v.x);
            __nv_bfloat16 h1 = __float2bfloat16(v.y);
            __nv_bfloat16 h2 = __float2bfloat16(v.z);
            __nv_bfloat16 h3 = __float2bfloat16(v.w);
            __nv_bfloat162 hiA; hiA.x = h0; hiA.y = h1;
            __nv_bfloat162 hiB; hiB.x = h2; hiB.y = h3;
            __nv_bfloat162 loA, loB;
            loA.x = __float2bfloat16(v.x - __bfloat162float(h0));
            loA.y = __float2bfloat16(v.y - __bfloat162float(h1));
            loB.x = __float2bfloat16(v.z - __bfloat162float(h2));
            loB.y = __float2bfloat16(v.w - __bfloat162float(h3));
            int e = lrow * LDA + lk0 + q * 4;
            *(__nv_bfloat162*)&sAhi[e]     = hiA;
            *(__nv_bfloat162*)&sAhi[e + 2] = hiB;
            *(__nv_bfloat162*)&sAlo[e]     = loA;
            *(__nv_bfloat162*)&sAlo[e + 2] = loB;
        }
        {
            uint4 vh0 = __ldg(bhp + ((ck + lk0) >> 3));
            uint4 vh1 = __ldg(bhp + ((ck + lk0) >> 3) + 1);
            uint4 vl0 = __ldg(blp + ((ck + lk0) >> 3));
            uint4 vl1 = __ldg(blp + ((ck + lk0) >> 3) + 1);
            int e = lrow * LDA + lk0;
            *(uint4*)&sBhi[e]     = vh0;
            *(uint4*)&sBhi[e + 8] = vh1;
            *(uint4*)&sBlo[e]     = vl0;
            *(uint4*)&sBlo[e + 8] = vl1;
        }
        __syncthreads();

#pragma unroll
        for (int k16 = 0; k16 < KS; k16 += 16) {
            uint32_t ah[2][4], al[2][4];
#pragma unroll
            for (int mi = 0; mi < 2; mi++) {
                int r0 = (wm + mi * 16 + group) * LDA + k16 + tid4 * 2;
                ah[mi][0] = *(const uint32_t*)&sAhi[r0];
                ah[mi][1] = *(const uint32_t*)&sAhi[r0 + 8 * LDA];
                ah[mi][2] = *(const uint32_t*)&sAhi[r0 + 8];
                ah[mi][3] = *(const uint32_t*)&sAhi[r0 + 8 * LDA + 8];
                al[mi][0] = *(const uint32_t*)&sAlo[r0];
                al[mi][1] = *(const uint32_t*)&sAlo[r0 + 8 * LDA];
                al[mi][2] = *(const uint32_t*)&sAlo[r0 + 8];
                al[mi][3] = *(const uint32_t*)&sAlo[r0 + 8 * LDA + 8];
            }
#pragma unroll
            for (int ni = 0; ni < 8; ni++) {
                int rb = (wn + ni * 8 + group) * LDA + k16 + tid4 * 2;
                uint32_t bh[2], bl[2];
                bh[0] = *(const uint32_t*)&sBhi[rb];
                bh[1] = *(const uint32_t*)&sBhi[rb + 8];
                bl[0] = *(const uint32_t*)&sBlo[rb];
                bl[1] = *(const uint32_t*)&sBlo[rb + 8];
#pragma unroll
                for (int mi = 0; mi < 2; mi++) {
                    mma_bf16(acc[mi][ni], ah[mi], bh);
                    mma_bf16(acc[mi][ni], ah[mi], bl);
                    mma_bf16(acc[mi][ni], al[mi], bh);
                }
            }
        }
    }

    // epilogue: add bias, store fp16
#pragma unroll
    for (int mi = 0; mi < 2; mi++) {
        int row0 = bm + wm + mi * 16 + group;
        int row1 = row0 + 8;
#pragma unroll
        for (int ni = 0; ni < 8; ni++) {
            int col = bn + wn + ni * 8 + tid4 * 2;
            float2 bb = *(const float2*)(g_bcat + col);
            if (row0 < NN) {
                __half2 o0 = __floats2half2_rn(acc[mi][ni][0] + bb.x, acc[mi][ni][1] + bb.y);
                *(__half2*)(g_featsh + (size_t)row0 * CO + col) = o0;
            }
            if (row1 < NN) {
                __half2 o1 = __floats2half2_rn(acc[mi][ni][2] + bb.x, acc[mi][ni][3] + bb.y);
                *(__half2*)(g_featsh + (size_t)row1 * CO + col) = o1;
            }
        }
    }
}

// ---------------- edge weights + flat CSR fill ----------------
__global__ void edge_kernel(const int* __restrict__ idx, const float* __restrict__ elem,
                            const float* __restrict__ aw, const float* __restrict__ ab) {
    int e = blockIdx.x * blockDim.x + threadIdx.x;
    if (e >= NE) return;
    int s = idx[e];
    int d = idx[NE + e];
    float el = elem[e];
    float4 as = __ldg(&g_as4[s]);
    float4 ad = __ldg(&g_ad4[d]);
    const float* asv = (const float*)&as;
    const float* adv = (const float*)&ad;
    float w[NH];
#pragma unroll
    for (int h = 0; h < NH; h++) {
        float sc = asv[h] + adv[h]
                 + __ldg(&aw[h * (2 * DO + 1) + 2 * DO]) * el + __ldg(&ab[h]);
        sc = sc * (1.0f / 20.0f);
        w[h] = __expf(-fmaxf(sc, 0.0f));
    }
    int pos = atomicAdd(&g_cursor[s], 1);
    g_cdst[pos] = d;
    *(float4*)(g_w + (size_t)pos * 4) = make_float4(w[0], w[1], w[2], w[3]);
}

// ---------------- per-node gather + normalize (32 thr/node, 8 nodes/block) ----------------
__global__ void __launch_bounds__(256) gather_kernel(float* __restrict__ out) {
    int t = threadIdx.x;
    int n = blockIdx.x * 8 + (t >> 5);
    int l = t & 31;              // lane handles elements l*8 .. l*8+7
    int h = l >> 3;              // head index = (l*8)/64
    int start = g_rowstart[n];
    int end = g_rowstart[n + 1];

    const uint4* fp = (const uint4*)g_featsh;   // 32 uint4 per row (256 half)
    float acc[8] = {};
    float wsum = 0.f;

#pragma unroll 4
    for (int j = start; j < end; j++) {
        int dst = __ldg(&g_cdst[j]);
        float w = __ldg(&g_w[(size_t)j * 4 + h]);
        uint4 f = __ldg(fp + (size_t)dst * 32 + l);
        float2 p0 = __half22float2(*(const __half2*)&f.x);
        float2 p1 = __half22float2(*(((const __half2*)&f.x) + 1));
        float2 p2 = __half22float2(*(const __half2*)&f.z);
        float2 p3 = __half22float2(*(((const __half2*)&f.z) + 1));
        acc[0] += w * p0.x;  acc[1] += w * p0.y;
        acc[2] += w * p1.x;  acc[3] += w * p1.y;
        acc[4] += w * p2.x;  acc[5] += w * p2.y;
        acc[6] += w * p3.x;  acc[7] += w * p3.y;
        wsum += w;
    }
    float inv = 1.0f / wsum;     // 0 edges -> inf -> 0*inf = NaN, matching reference
    float4 o0 = make_float4(acc[0] * inv, acc[1] * inv, acc[2] * inv, acc[3] * inv);
    float4 o1 = make_float4(acc[4] * inv, acc[5] * inv, acc[6] * inv, acc[7] * inv);
    float* op = out + (size_t)n * CO + l * 8;
    *(float4*)(op)     = o0;
    *(float4*)(op + 4) = o1;
}

extern "C" void kernel_launch(void* const* d_in, const int* in_sizes, int n_in,
                              void* d_out, int out_size) {
    const float* x    = (const float*)d_in[0];
    const int*   idx  = (const int*)d_in[1];
    const float* elem = (const float*)d_in[2];
    const float* Ws   = (const float*)d_in[3];
    const float* bs   = (const float*)d_in[4];
    const float* aw   = (const float*)d_in[5];
    const float* ab   = (const float*)d_in[6];
    float* out = (float*)d_out;

    static cudaStream_t s1 = nullptr, s2 = nullptr;
    static cudaEvent_t evF = nullptr, evPv = nullptr, evAs = nullptr, evJ = nullptr;
    if (!s1) {   // created on the (uncaptured) correctness call, reused thereafter
        cudaStreamCreateWithFlags(&s1, cudaStreamNonBlocking);
        cudaStreamCreateWithFlags(&s2, cudaStreamNonBlocking);
        cudaEventCreateWithFlags(&evF, cudaEventDisableTiming);
        cudaEventCreateWithFlags(&evPv, cudaEventDisableTiming);
        cudaEventCreateWithFlags(&evAs, cudaEventDisableTiming);
        cudaEventCreateWithFlags(&evJ, cudaEventDisableTiming);
    }

    // fork from origin (legacy) stream
    cudaEventRecord(evF, 0);
    cudaStreamWaitEvent(s1, evF, 0);

    // s1: prepv first, then CSR chain
    prepv_kernel<<<(8 * DI + 8 + 255) / 256, 256, 0, s1>>>(Ws, bs, aw);
    cudaEventRecord(evPv, s1);
    zero_deg_kernel<<<(NN + 255) / 256, 256, 0, s1>>>();
    count_kernel<<<(NE + 255) / 256, 256, 0, s1>>>(idx);
    scan1_kernel<<<NB_SCAN, 256, 0, s1>>>();
    scan2_kernel<<<1, 256, 0, s1>>>();
    scan3_kernel<<<NB_SCAN, 256, 0, s1>>>();

    // s2: attention dots (needs only prepv; overlaps count/scan)
    cudaStreamWaitEvent(s2, evPv, 0);
    as_kernel<<<(NN * 32 + 255) / 256, 256, 0, s2>>>(x);
    cudaEventRecord(evAs, s2);

    // s1: edge needs scan (same stream) + as (cross-stream)
    cudaStreamWaitEvent(s1, evAs, 0);
    edge_kernel<<<(NE + 255) / 256, 256, 0, s1>>>(idx, elem, aw, ab);
    cudaEventRecord(evJ, s1);

    // legacy stream: GEMM chain (overlaps s1/s2)
    prep_kernel<<<1, 256>>>(bs);
    prepB_kernel<<<(CO * DI + 255) / 256, 256>>>(Ws);
    gemm_mma_kernel<<<dim3(2, (NN + 127) / 128), 256>>>(x);

    // join, then gather (needs feats + CSR + weights)
    cudaStreamWaitEvent(0, evJ, 0);
    gather_kernel<<<(NN + 7) / 8, 256>>>(out);
}

// round 9
// speedup vs baseline: 1.1845x; 1.0418x over previous
#include <cuda_runtime.h>
#include <cuda_bf16.h>
#include <cuda_fp16.h>
#include <cstdint>

#define NN 50000
#define NE 800000
#define NH 4
#define DI 256
#define DO 64
#define CO 256   // NH * DO

#define NB_SCAN 196  // ceil(NN/256)

// ---- scratch (device globals; no runtime allocation) ----
__device__ __half g_featsh[NN * CO];     // [n][h*64+o] fp16
__device__ float4 g_as4[NN];
__device__ float4 g_ad4[NN];
__device__ float g_w[NE * NH];           // CSR-ordered weights [pos][h]
__device__ int   g_cdst[NE];
__device__ int   g_deg[NN];
__device__ int   g_rowstart[NN + 1];
__device__ int   g_cursor[NN];
__device__ float g_bcat[CO];
__device__ int   g_part[NB_SCAN];
__device__ float g_v[8 * DI];
__device__ float g_c[8];
__device__ __nv_bfloat16 g_Bhi[CO * DI]; // Bt[n][k] hi  (n = h*64+o, k = d)
__device__ __nv_bfloat16 g_Blo[CO * DI]; // Bt[n][k] lo

// ==================== small prep kernels ====================
__global__ void prep_kernel(const float* __restrict__ bs) {
    int i = blockIdx.x * blockDim.x + threadIdx.x;
    if (i < CO) {
        int h = i >> 6, o = i & 63;
        g_bcat[i] = bs[h * DO + o];
    }
}

// B transposed + bf16 split: Bt[n][k] = Ws[h][k][o], n = h*64+o
__global__ void prepB_kernel(const float* __restrict__ Ws) {
    int i = blockIdx.x * blockDim.x + threadIdx.x;
    if (i >= CO * DI) return;
    int n = i >> 8, k = i & 255;
    int h = n >> 6, o = n & 63;
    float v = Ws[(h * DI + k) * DO + o];
    __nv_bfloat16 hi = __float2bfloat16(v);
    __nv_bfloat16 lo = __float2bfloat16(v - __bfloat162float(hi));
    g_Bhi[i] = hi;
    g_Blo[i] = lo;
}

// fused: v/c dot products + deg zeroing (covers max(NN, 8*DI+8) threads)
__global__ void prepv_zero_kernel(const float* __restrict__ Ws, const float* __restrict__ bs,
                                  const float* __restrict__ aw) {
    int id = blockIdx.x * blockDim.x + threadIdx.x;
    if (id < 8 * DI) {
        int j = id >> 8, d = id & 255;
        int h = j >> 1, sd = j & 1;
        const float* wrow = Ws + (h * DI + d) * DO;
        const float* arow = aw + h * (2 * DO + 1) + sd * DO;
        float s = 0.f;
#pragma unroll
        for (int o = 0; o < DO; o++) s += wrow[o] * arow[o];
        g_v[id] = s;
    } else if (id < 8 * DI + 8) {
        int j = id - 8 * DI;
        int h = j >> 1, sd = j & 1;
        const float* arow = aw + h * (2 * DO + 1) + sd * DO;
        float s = 0.f;
#pragma unroll
        for (int o = 0; o < DO; o++) s += bs[h * DO + o] * arow[o];
        g_c[j] = s;
    }
    if (id < NN) g_deg[id] = 0;
}

__global__ void count_kernel(const int* __restrict__ idx) {
    int e = blockIdx.x * blockDim.x + threadIdx.x;
    if (e < NE) atomicAdd(&g_deg[idx[e]], 1);
}

// ---------------- 3-phase decoupled scan ----------------
__global__ void scan1_kernel() {
    __shared__ int sd[256];
    int tid = threadIdx.x;
    int i = blockIdx.x * 256 + tid;
    sd[tid] = (i < NN) ? g_deg[i] : 0;
    __syncthreads();
    for (int off = 128; off; off >>= 1) {
        if (tid < off) sd[tid] += sd[tid + off];
        __syncthreads();
    }
    if (tid == 0) g_part[blockIdx.x] = sd[0];
}

__global__ void scan2_kernel() {
    __shared__ int sd[256];
    int tid = threadIdx.x;
    int v = (tid < NB_SCAN) ? g_part[tid] : 0;
    sd[tid] = v;
    __syncthreads();
    for (int off = 1; off < 256; off <<= 1) {
        int t = (tid >= off) ? sd[tid - off] : 0;
        __syncthreads();
        sd[tid] += t;
        __syncthreads();
    }
    if (tid < NB_SCAN) g_part[tid] = sd[tid] - v;
    if (tid == 255) g_rowstart[NN] = sd[255];
}

__global__ void scan3_kernel() {
    __shared__ int sd[256];
    int tid = threadIdx.x;
    int i = blockIdx.x * 256 + tid;
    int v = (i < NN) ? g_deg[i] : 0;
    sd[tid] = v;
    __syncthreads();
    for (int off = 1; off < 256; off <<= 1) {
        int t = (tid >= off) ? sd[tid - off] : 0;
        __syncthreads();
        sd[tid] += t;
        __syncthreads();
    }
    if (i < NN) {
        int ex = g_part[blockIdx.x] + sd[tid] - v;
        g_rowstart[i] = ex;
        g_cursor[i] = ex;
    }
}

// ---------------- a_s/a_d directly from x: warp per node ----------------
__global__ void __launch_bounds__(256) as_kernel(const float* __restrict__ x) {
    int gw = (blockIdx.x * blockDim.x + threadIdx.x) >> 5;
    int lane = threadIdx.x & 31;
    if (gw >= NN) return;
    const float* xr = x + (size_t)gw * DI;
    float a[8] = {};
#pragma unroll
    for (int c8 = 0; c8 < 8; c8++) {
        float xv = xr[c8 * 32 + lane];
#pragma unroll
        for (int j = 0; j < 8; j++)
            a[j] += xv * __ldg(&g_v[j * DI + c8 * 32 + lane]);
    }
#pragma unroll
    for (int j = 0; j < 8; j++) {
#pragma unroll
        for (int off = 16; off; off >>= 1)
            a[j] += __shfl_xor_sync(0xffffffffu, a[j], off);
    }
    if (lane == 0) {
        g_as4[gw] = make_float4(a[0] + g_c[0], a[2] + g_c[2],
                                a[4] + g_c[4], a[6] + g_c[6]);
        g_ad4[gw] = make_float4(a[1] + g_c[1], a[3] + g_c[3],
                                a[5] + g_c[5], a[7] + g_c[7]);
    }
}

// ==================== warp-level bf16 split MMA GEMM ====================
#define KS 32          // k-chunk
#define LDA 40         // smem row stride in bf16 elements

__device__ __forceinline__ void mma_bf16(float* c, const uint32_t* a, const uint32_t* b) {
    asm volatile(
        "mma.sync.aligned.m16n8k16.row.col.f32.bf16.bf16.f32 "
        "{%0,%1,%2,%3}, {%4,%5,%6,%7}, {%8,%9}, {%0,%1,%2,%3};"
        : "+f"(c[0]), "+f"(c[1]), "+f"(c[2]), "+f"(c[3])
        : "r"(a[0]), "r"(a[1]), "r"(a[2]), "r"(a[3]), "r"(b[0]), "r"(b[1]));
}

__global__ void __launch_bounds__(256, 2) gemm_mma_kernel(const float* __restrict__ x) {
    __shared__ __align__(16) __nv_bfloat16 sAhi[128 * LDA];
    __shared__ __align__(16) __nv_bfloat16 sAlo[128 * LDA];
    __shared__ __align__(16) __nv_bfloat16 sBhi[128 * LDA];
    __shared__ __align__(16) __nv_bfloat16 sBlo[128 * LDA];

    int tid = threadIdx.x;
    int wid = tid >> 5;
    int lane = tid & 31;
    int group = lane >> 2;
    int tid4 = lane & 3;
    int bm = blockIdx.y * 128;
    int bn = blockIdx.x * 128;
    int wm = (wid & 3) * 32;
    int wn = (wid >> 2) * 64;

    int lrow = tid >> 1;
    int lk0 = (tid & 1) * 16;
    int grow = bm + lrow;
    bool aok = grow < NN;
    const float4* xp = (const float4*)(x + (size_t)grow * DI);
    const uint4* bhp = (const uint4*)(g_Bhi + (size_t)(bn + lrow) * DI);
    const uint4* blp = (const uint4*)(g_Blo + (size_t)(bn + lrow) * DI);

    float acc[2][8][4] = {};

    for (int c = 0; c < DI / KS; c++) {
        if (c) __syncthreads();
        int ck = c * KS;
#pragma unroll
        for (int q = 0; q < 4; q++) {
            float4 v = aok ? __ldg(xp + ((ck + lk0) >> 2) + q)
                           : make_float4(0.f, 0.f, 0.f, 0.f);
            __nv_bfloat16 h0 = __float2bfloat16(v.x);
            __nv_bfloat16 h1 = __float2bfloat16(v.y);
            __nv_bfloat16 h2 = __float2bfloat16(v.z);
            __nv_bfloat16 h3 = __float2bfloat16(v.w);
            __nv_bfloat162 hiA; hiA.x = h0; hiA.y = h1;
            __nv_bfloat162 hiB; hiB.x = h2; hiB.y = h3;
            __nv_bfloat162 loA, loB;
            loA.x = __float2bfloat16(v.x - __bfloat162float(h0));
            loA.y = __float2bfloat16(v.y - __bfloat162float(h1));
            loB.x = __float2bfloat16(v.z - __bfloat162float(h2));
            loB.y = __float2bfloat16(v.w - __bfloat162float(h3));
            int e = lrow * LDA + lk0 + q * 4;
            *(__nv_bfloat162*)&sAhi[e]     = hiA;
            *(__nv_bfloat162*)&sAhi[e + 2] = hiB;
            *(__nv_bfloat162*)&sAlo[e]     = loA;
            *(__nv_bfloat162*)&sAlo[e + 2] = loB;
        }
        {
            uint4 vh0 = __ldg(bhp + ((ck + lk0) >> 3));
            uint4 vh1 = __ldg(bhp + ((ck + lk0) >> 3) + 1);
            uint4 vl0 = __ldg(blp + ((ck + lk0) >> 3));
            uint4 vl1 = __ldg(blp + ((ck + lk0) >> 3) + 1);
            int e = lrow * LDA + lk0;
            *(uint4*)&sBhi[e]     = vh0;
            *(uint4*)&sBhi[e + 8] = vh1;
            *(uint4*)&sBlo[e]     = vl0;
            *(uint4*)&sBlo[e + 8] = vl1;
        }
        __syncthreads();

#pragma unroll
        for (int k16 = 0; k16 < KS; k16 += 16) {
            uint32_t ah[2][4], al[2][4];
#pragma unroll
            for (int mi = 0; mi < 2; mi++) {
                int r0 = (wm + mi * 16 + group) * LDA + k16 + tid4 * 2;
                ah[mi][0] = *(const uint32_t*)&sAhi[r0];
                ah[mi][1] = *(const uint32_t*)&sAhi[r0 + 8 * LDA];
                ah[mi][2] = *(const uint32_t*)&sAhi[r0 + 8];
                ah[mi][3] = *(const uint32_t*)&sAhi[r0 + 8 * LDA + 8];
                al[mi][0] = *(const uint32_t*)&sAlo[r0];
                al[mi][1] = *(const uint32_t*)&sAlo[r0 + 8 * LDA];
                al[mi][2] = *(const uint32_t*)&sAlo[r0 + 8];
                al[mi][3] = *(const uint32_t*)&sAlo[r0 + 8 * LDA + 8];
            }
#pragma unroll
            for (int ni = 0; ni < 8; ni++) {
                int rb = (wn + ni * 8 + group) * LDA + k16 + tid4 * 2;
                uint32_t bh[2], bl[2];
                bh[0] = *(const uint32_t*)&sBhi[rb];
                bh[1] = *(const uint32_t*)&sBhi[rb + 8];
                bl[0] = *(const uint32_t*)&sBlo[rb];
                bl[1] = *(const uint32_t*)&sBlo[rb + 8];
#pragma unroll
                for (int mi = 0; mi < 2; mi++) {
                    mma_bf16(acc[mi][ni], ah[mi], bh);
                    mma_bf16(acc[mi][ni], ah[mi], bl);
                    mma_bf16(acc[mi][ni], al[mi], bh);
                }
            }
        }
    }

    // epilogue: add bias, store fp16
#pragma unroll
    for (int mi = 0; mi < 2; mi++) {
        int row0 = bm + wm + mi * 16 + group;
        int row1 = row0 + 8;
#pragma unroll
        for (int ni = 0; ni < 8; ni++) {
            int col = bn + wn + ni * 8 + tid4 * 2;
            float2 bb = *(const float2*)(g_bcat + col);
            if (row0 < NN) {
                __half2 o0 = __floats2half2_rn(acc[mi][ni][0] + bb.x, acc[mi][ni][1] + bb.y);
                *(__half2*)(g_featsh + (size_t)row0 * CO + col) = o0;
            }
            if (row1 < NN) {
                __half2 o1 = __floats2half2_rn(acc[mi][ni][2] + bb.x, acc[mi][ni][3] + bb.y);
                *(__half2*)(g_featsh + (size_t)row1 * CO + col) = o1;
            }
        }
    }
}

// ---------------- edge weights + flat CSR fill ----------------
__global__ void edge_kernel(const int* __restrict__ idx, const float* __restrict__ elem,
                            const float* __restrict__ aw, const float* __restrict__ ab) {
    int e = blockIdx.x * blockDim.x + threadIdx.x;
    if (e >= NE) return;
    int s = idx[e];
    int d = idx[NE + e];
    float el = elem[e];
    float4 as = __ldg(&g_as4[s]);
    float4 ad = __ldg(&g_ad4[d]);
    const float* asv = (const float*)&as;
    const float* adv = (const float*)&ad;
    float w[NH];
#pragma unroll
    for (int h = 0; h < NH; h++) {
        float sc = asv[h] + adv[h]
                 + __ldg(&aw[h * (2 * DO + 1) + 2 * DO]) * el + __ldg(&ab[h]);
        sc = sc * (1.0f / 20.0f);
        w[h] = __expf(-fmaxf(sc, 0.0f));
    }
    int pos = atomicAdd(&g_cursor[s], 1);
    g_cdst[pos] = d;
    *(float4*)(g_w + (size_t)pos * 4) = make_float4(w[0], w[1], w[2], w[3]);
}

// ---------------- per-node gather + normalize (32 thr/node, 8 nodes/block) ----------------
// explicit 4-wide software pipeline for MLP on the feats gather
__global__ void __launch_bounds__(256) gather_kernel(float* __restrict__ out) {
    int t = threadIdx.x;
    int n = blockIdx.x * 8 + (t >> 5);
    int l = t & 31;              // lane handles elements l*8 .. l*8+7
    int h = l >> 3;              // head index = (l*8)/64
    int start = g_rowstart[n];
    int end = g_rowstart[n + 1];

    const uint4* fp = (const uint4*)g_featsh;   // 32 uint4 per row (256 half)
    float acc[8] = {};
    float wsum = 0.f;

    int j = start;
    for (; j + 4 <= end; j += 4) {
        // 4 independent index loads
        int d0 = __ldg(&g_cdst[j + 0]);
        int d1 = __ldg(&g_cdst[j + 1]);
        int d2 = __ldg(&g_cdst[j + 2]);
        int d3 = __ldg(&g_cdst[j + 3]);
        // 4 independent weight loads
        float w0 = __ldg(&g_w[(size_t)(j + 0) * 4 + h]);
        float w1 = __ldg(&g_w[(size_t)(j + 1) * 4 + h]);
        float w2 = __ldg(&g_w[(size_t)(j + 2) * 4 + h]);
        float w3 = __ldg(&g_w[(size_t)(j + 3) * 4 + h]);
        // 4 independent feats loads (all in flight together)
        uint4 f0 = __ldg(fp + (size_t)d0 * 32 + l);
        uint4 f1 = __ldg(fp + (size_t)d1 * 32 + l);
        uint4 f2 = __ldg(fp + (size_t)d2 * 32 + l);
        uint4 f3 = __ldg(fp + (size_t)d3 * 32 + l);

#define ACCUM(F, W) do {                                              \
        float2 p0 = __half22float2(*(const __half2*)&(F).x);          \
        float2 p1 = __half22float2(*(((const __half2*)&(F).x) + 1));  \
        float2 p2 = __half22float2(*(const __half2*)&(F).z);          \
        float2 p3 = __half22float2(*(((const __half2*)&(F).z) + 1));  \
        acc[0] += (W) * p0.x;  acc[1] += (W) * p0.y;                  \
        acc[2] += (W) * p1.x;  acc[3] += (W) * p1.y;                  \
        acc[4] += (W) * p2.x;  acc[5] += (W) * p2.y;                  \
        acc[6] += (W) * p3.x;  acc[7] += (W) * p3.y;                  \
        wsum += (W);                                                  \
    } while (0)

        ACCUM(f0, w0);
        ACCUM(f1, w1);
        ACCUM(f2, w2);
        ACCUM(f3, w3);
    }
    for (; j < end; j++) {
        int dst = __ldg(&g_cdst[j]);
        float w = __ldg(&g_w[(size_t)j * 4 + h]);
        uint4 f = __ldg(fp + (size_t)dst * 32 + l);
        ACCUM(f, w);
    }
#undef ACCUM

    float inv = 1.0f / wsum;     // 0 edges -> inf -> 0*inf = NaN, matching reference
    float4 o0 = make_float4(acc[0] * inv, acc[1] * inv, acc[2] * inv, acc[3] * inv);
    float4 o1 = make_float4(acc[4] * inv, acc[5] * inv, acc[6] * inv, acc[7] * inv);
    float* op = out + (size_t)n * CO + l * 8;
    *(float4*)(op)     = o0;
    *(float4*)(op + 4) = o1;
}

extern "C" void kernel_launch(void* const* d_in, const int* in_sizes, int n_in,
                              void* d_out, int out_size) {
    const float* x    = (const float*)d_in[0];
    const int*   idx  = (const int*)d_in[1];
    const float* elem = (const float*)d_in[2];
    const float* Ws   = (const float*)d_in[3];
    const float* bs   = (const float*)d_in[4];
    const float* aw   = (const float*)d_in[5];
    const float* ab   = (const float*)d_in[6];
    float* out = (float*)d_out;

    static cudaStream_t s1 = nullptr, s2 = nullptr;
    static cudaEvent_t evF = nullptr, evPv = nullptr, evAs = nullptr, evJ = nullptr;
    if (!s1) {   // created on the (uncaptured) correctness call, reused thereafter
        cudaStreamCreateWithFlags(&s1, cudaStreamNonBlocking);
        cudaStreamCreateWithFlags(&s2, cudaStreamNonBlocking);
        cudaEventCreateWithFlags(&evF, cudaEventDisableTiming);
        cudaEventCreateWithFlags(&evPv, cudaEventDisableTiming);
        cudaEventCreateWithFlags(&evAs, cudaEventDisableTiming);
        cudaEventCreateWithFlags(&evJ, cudaEventDisableTiming);
    }

    // fork from origin (legacy) stream
    cudaEventRecord(evF, 0);
    cudaStreamWaitEvent(s1, evF, 0);

    // launch #1: fused prepv + deg zero (s1)
    prepv_zero_kernel<<<(NN + 255) / 256, 256, 0, s1>>>(Ws, bs, aw);
    cudaEventRecord(evPv, s1);

    // launches #2-3: legacy GEMM prep
    prep_kernel<<<1, 256>>>(bs);
    prepB_kernel<<<(CO * DI + 255) / 256, 256>>>(Ws);

    // launches #4-5: s1 CSR chain start
    count_kernel<<<(NE + 255) / 256, 256, 0, s1>>>(idx);
    scan1_kernel<<<NB_SCAN, 256, 0, s1>>>();

    // launch #6: GEMM (profiled by ncu -s 5 -c 1)
    gemm_mma_kernel<<<dim3(2, (NN + 127) / 128), 256>>>(x);

    // s1: rest of scan
    scan2_kernel<<<1, 256, 0, s1>>>();
    scan3_kernel<<<NB_SCAN, 256, 0, s1>>>();

    // s2: attention dots (needs only prepv; overlaps count/scan)
    cudaStreamWaitEvent(s2, evPv, 0);
    as_kernel<<<(NN * 32 + 255) / 256, 256, 0, s2>>>(x);
    cudaEventRecord(evAs, s2);

    // s1: edge needs scan (same stream) + as (cross-stream)
    cudaStreamWaitEvent(s1, evAs, 0);
    edge_kernel<<<(NE + 255) / 256, 256, 0, s1>>>(idx, elem, aw, ab);
    cudaEventRecord(evJ, s1);

    // join, then gather (needs feats + CSR + weights)
    cudaStreamWaitEvent(0, evJ, 0);
    gather_kernel<<<(NN + 7) / 8, 256>>>(out);
}